// round 1
// baseline (speedup 1.0000x reference)
#include <cuda_runtime.h>

// Problem shape (fixed by the dataset)
#define NB      32
#define CCH     192
#define HW      112
#define IMG     (HW*HW)           // 12544
#define TILE_H  16
#define TILES   (HW / TILE_H)     // 7
#define PITCH   116               // smem row pitch (multiple of 4 for float4)
#define SROWS   (TILE_H + 2)      // 18
#define SMEMN   (SROWS * PITCH)   // 2088
#define NTHREADS 256
#define QUADS   (TILE_H * (HW/4)) // 448 quads of 4 pixels per tile
#define NHW_F   ((float)(NB * IMG))
#define BN_EPS  1e-5f

// Scratch for channel statistics / folded affine params (no cudaMalloc allowed)
__device__ float g_sum[CCH];
__device__ float g_sumsq[CCH];
__device__ float g_scale[CCH];
__device__ float g_shift[CCH];

__global__ void zero_stats_kernel() {
    int i = threadIdx.x;
    if (i < CCH) { g_sum[i] = 0.f; g_sumsq[i] = 0.f; }
}

// Load an (TILE_H+2) x (HW+2) halo tile (zero-padded) into smem with pitch PITCH.
__device__ __forceinline__ void load_tile(const float* __restrict__ base,
                                          int h0, float* sm) {
    #pragma unroll 2
    for (int idx = threadIdx.x; idx < SMEMN; idx += NTHREADS) {
        int r  = idx / PITCH;
        int cc = idx - r * PITCH;
        int gh = h0 - 1 + r;
        int gw = cc - 1;
        float v = 0.f;
        if ((unsigned)gh < HW && (unsigned)gw < HW)
            v = __ldg(base + gh * HW + gw);
        sm[idx] = v;
    }
}

// Compute 4 horizontal conv outputs for quad (r, w4) from smem tile.
__device__ __forceinline__ void conv_quad(const float* __restrict__ sm,
                                          const float* __restrict__ k,
                                          float bias, int r, int w4,
                                          float& a0, float& a1, float& a2, float& a3) {
    a0 = bias; a1 = bias; a2 = bias; a3 = bias;
    #pragma unroll
    for (int i = 0; i < 3; i++) {
        const float* row = &sm[(r + i) * PITCH + w4];
        float4 v = *reinterpret_cast<const float4*>(row);
        float2 u = *reinterpret_cast<const float2*>(row + 4);
        float k0 = k[i * 3 + 0], k1 = k[i * 3 + 1], k2 = k[i * 3 + 2];
        a0 += k0 * v.x + k1 * v.y + k2 * v.z;
        a1 += k0 * v.y + k1 * v.z + k2 * v.w;
        a2 += k0 * v.z + k1 * v.w + k2 * u.x;
        a3 += k0 * v.w + k1 * u.x + k2 * u.y;
    }
}

// Pass 1: conv+bias on the fly, accumulate per-channel sum and sum of squares.
__global__ void __launch_bounds__(NTHREADS)
stats_kernel(const float* __restrict__ in,
             const float* __restrict__ w,
             const float* __restrict__ b) {
    __shared__ __align__(16) float sm[SMEMN];
    __shared__ float red1[NTHREADS / 32];
    __shared__ float red2[NTHREADS / 32];

    int bid = blockIdx.x;
    int t = bid % TILES;
    int c = (bid / TILES) % CCH;
    int n = bid / (TILES * CCH);
    int h0 = t * TILE_H;

    const float* base = in + (size_t)(n * CCH + c) * IMG;
    load_tile(base, h0, sm);

    float k[9];
    #pragma unroll
    for (int i = 0; i < 9; i++) k[i] = __ldg(w + c * 9 + i);
    float bias = __ldg(b + c);
    __syncthreads();

    float s1 = 0.f, s2 = 0.f;
    for (int q = threadIdx.x; q < QUADS; q += NTHREADS) {
        int r  = q / (HW / 4);
        int w4 = (q - r * (HW / 4)) * 4;
        float a0, a1, a2, a3;
        conv_quad(sm, k, bias, r, w4, a0, a1, a2, a3);
        s1 += (a0 + a1) + (a2 + a3);
        s2 += (a0 * a0 + a1 * a1) + (a2 * a2 + a3 * a3);
    }

    // block reduction
    #pragma unroll
    for (int off = 16; off > 0; off >>= 1) {
        s1 += __shfl_down_sync(0xFFFFFFFFu, s1, off);
        s2 += __shfl_down_sync(0xFFFFFFFFu, s2, off);
    }
    int lane = threadIdx.x & 31;
    int wid  = threadIdx.x >> 5;
    if (lane == 0) { red1[wid] = s1; red2[wid] = s2; }
    __syncthreads();
    if (wid == 0) {
        s1 = (lane < NTHREADS / 32) ? red1[lane] : 0.f;
        s2 = (lane < NTHREADS / 32) ? red2[lane] : 0.f;
        #pragma unroll
        for (int off = 4; off > 0; off >>= 1) {
            s1 += __shfl_down_sync(0xFFFFFFFFu, s1, off);
            s2 += __shfl_down_sync(0xFFFFFFFFu, s2, off);
        }
        if (lane == 0) {
            atomicAdd(&g_sum[c], s1);
            atomicAdd(&g_sumsq[c], s2);
        }
    }
}

// Fold mean/var/gamma/beta into per-channel scale & shift.
__global__ void finalize_kernel(const float* __restrict__ gamma,
                                const float* __restrict__ beta) {
    int c = threadIdx.x;
    if (c < CCH) {
        float mean = g_sum[c] / NHW_F;
        float var  = g_sumsq[c] / NHW_F - mean * mean;
        float sc   = gamma[c] * rsqrtf(var + BN_EPS);
        g_scale[c] = sc;
        g_shift[c] = beta[c] - sc * mean;
    }
}

// Pass 2: recompute conv+bias, apply scale/shift + ReLU6, write float4.
__global__ void __launch_bounds__(NTHREADS)
output_kernel(const float* __restrict__ in,
              const float* __restrict__ w,
              const float* __restrict__ b,
              float* __restrict__ out) {
    __shared__ __align__(16) float sm[SMEMN];

    int bid = blockIdx.x;
    int t = bid % TILES;
    int c = (bid / TILES) % CCH;
    int n = bid / (TILES * CCH);
    int h0 = t * TILE_H;

    const float* base = in + (size_t)(n * CCH + c) * IMG;
    load_tile(base, h0, sm);

    float k[9];
    #pragma unroll
    for (int i = 0; i < 9; i++) k[i] = __ldg(w + c * 9 + i);
    float bias = __ldg(b + c);
    float sc = g_scale[c];
    float sh = g_shift[c];
    __syncthreads();

    float* obase = out + (size_t)(n * CCH + c) * IMG;
    for (int q = threadIdx.x; q < QUADS; q += NTHREADS) {
        int r  = q / (HW / 4);
        int w4 = (q - r * (HW / 4)) * 4;
        float a0, a1, a2, a3;
        conv_quad(sm, k, bias, r, w4, a0, a1, a2, a3);
        float4 o;
        o.x = fminf(fmaxf(a0 * sc + sh, 0.f), 6.f);
        o.y = fminf(fmaxf(a1 * sc + sh, 0.f), 6.f);
        o.z = fminf(fmaxf(a2 * sc + sh, 0.f), 6.f);
        o.w = fminf(fmaxf(a3 * sc + sh, 0.f), 6.f);
        *reinterpret_cast<float4*>(obase + (h0 + r) * HW + w4) = o;
    }
}

extern "C" void kernel_launch(void* const* d_in, const int* in_sizes, int n_in,
                              void* d_out, int out_size) {
    const float* in    = (const float*)d_in[0];
    const float* w     = (const float*)d_in[1];
    const float* b     = (const float*)d_in[2];
    const float* gamma = (const float*)d_in[3];
    const float* beta  = (const float*)d_in[4];
    float* out = (float*)d_out;

    int grid = NB * CCH * TILES;  // 43008 blocks
    zero_stats_kernel<<<1, CCH>>>();
    stats_kernel<<<grid, NTHREADS>>>(in, w, b);
    finalize_kernel<<<1, CCH>>>(gamma, beta);
    output_kernel<<<grid, NTHREADS>>>(in, w, b, out);
}

// round 2
// speedup vs baseline: 1.4069x; 1.4069x over previous
#include <cuda_runtime.h>

// Problem shape (fixed by the dataset)
#define NB      32
#define CCH     192
#define HW      112
#define IMG     (HW*HW)           // 12544
#define TILE_H  16
#define TILES   (HW / TILE_H)     // 7
#define PITCH   116               // smem row pitch in floats (116*4 B, 16B-aligned rows)
#define SROWS   (TILE_H + 2)      // 18
#define SMEMN   (SROWS * PITCH)
#define NTHREADS 224              // 7 warps: 28 quad-columns x 8 row-pairs
#define NHW_F   ((float)(NB * IMG))
#define BN_EPS  1e-5f

// Scratch for channel statistics / folded affine params (no cudaMalloc allowed)
__device__ float g_sum[CCH];
__device__ float g_sumsq[CCH];
__device__ float g_scale[CCH];
__device__ float g_shift[CCH];

__global__ void zero_stats_kernel() {
    int i = threadIdx.x;
    if (i < CCH) { g_sum[i] = 0.f; g_sumsq[i] = 0.f; }
}

// Fill padded tile: sm[r][1+c] = in[h0-1+r][c] (zero outside image).
// Columns 0 and 113..115 are the left/right halo -> always zero (image border).
__device__ __forceinline__ void load_tile(const float* __restrict__ base,
                                          int h0, float* __restrict__ sm) {
    #pragma unroll 3
    for (int s = threadIdx.x; s < SROWS * 28; s += NTHREADS) {
        int r  = s / 28;
        int c4 = s - r * 28;
        int gh = h0 - 1 + r;
        float4 v = make_float4(0.f, 0.f, 0.f, 0.f);
        if ((unsigned)gh < HW)
            v = __ldg(reinterpret_cast<const float4*>(base + gh * HW) + c4);
        float* d = &sm[r * PITCH + 1 + c4 * 4];
        d[0] = v.x; d[1] = v.y; d[2] = v.z; d[3] = v.w;
    }
    if (threadIdx.x < SROWS) {
        float* row = &sm[threadIdx.x * PITCH];
        row[0] = 0.f; row[113] = 0.f; row[114] = 0.f; row[115] = 0.f;
    }
}

__device__ __forceinline__ void load6(const float* __restrict__ p, float* d) {
    float4 v = *reinterpret_cast<const float4*>(p);      // 16B-aligned
    float2 u = *reinterpret_cast<const float2*>(p + 4);  // 8B-aligned
    d[0] = v.x; d[1] = v.y; d[2] = v.z; d[3] = v.w; d[4] = u.x; d[5] = u.y;
}

// Compute a 4-wide x 2-high micro-tile of conv+bias results.
// ry in 0..7 selects the row pair; x4 = image column of first output.
__device__ __forceinline__ void conv42(const float* __restrict__ sm,
                                       const float* __restrict__ k, float bias,
                                       int ry, int x4,
                                       float* a, float* bb) {
    float p0[6], p1[6], p2[6], p3[6];
    const float* rbase = &sm[(2 * ry) * PITCH + x4];
    load6(rbase,             p0);
    load6(rbase + PITCH,     p1);
    load6(rbase + 2 * PITCH, p2);
    load6(rbase + 3 * PITCH, p3);
    #pragma unroll
    for (int i = 0; i < 4; i++) {
        a[i] = bias
             + k[0] * p0[i] + k[1] * p0[i + 1] + k[2] * p0[i + 2]
             + k[3] * p1[i] + k[4] * p1[i + 1] + k[5] * p1[i + 2]
             + k[6] * p2[i] + k[7] * p2[i + 1] + k[8] * p2[i + 2];
        bb[i] = bias
              + k[0] * p1[i] + k[1] * p1[i + 1] + k[2] * p1[i + 2]
              + k[3] * p2[i] + k[4] * p2[i + 1] + k[5] * p2[i + 2]
              + k[6] * p3[i] + k[7] * p3[i + 1] + k[8] * p3[i + 2];
    }
}

// Pass 1: conv+bias on the fly, accumulate per-channel sum and sum of squares.
__global__ void __launch_bounds__(NTHREADS)
stats_kernel(const float* __restrict__ in,
             const float* __restrict__ w,
             const float* __restrict__ b) {
    __shared__ __align__(16) float sm[SMEMN];
    __shared__ float red1[NTHREADS / 32];
    __shared__ float red2[NTHREADS / 32];

    int h0 = blockIdx.x * TILE_H;
    int c  = blockIdx.y;
    int n  = blockIdx.z;

    const float* base = in + (size_t)(n * CCH + c) * IMG;
    load_tile(base, h0, sm);

    float k[9];
    #pragma unroll
    for (int i = 0; i < 9; i++) k[i] = __ldg(w + c * 9 + i);
    float bias = __ldg(b + c);
    __syncthreads();

    int ry = threadIdx.x / 28;
    int x4 = (threadIdx.x - ry * 28) * 4;

    float a[4], bb[4];
    conv42(sm, k, bias, ry, x4, a, bb);

    float s1 = 0.f, s2 = 0.f;
    #pragma unroll
    for (int i = 0; i < 4; i++) {
        s1 += a[i] + bb[i];
        s2 += a[i] * a[i] + bb[i] * bb[i];
    }

    // block reduction (7 warps)
    #pragma unroll
    for (int off = 16; off > 0; off >>= 1) {
        s1 += __shfl_down_sync(0xFFFFFFFFu, s1, off);
        s2 += __shfl_down_sync(0xFFFFFFFFu, s2, off);
    }
    int lane = threadIdx.x & 31;
    int wid  = threadIdx.x >> 5;
    if (lane == 0) { red1[wid] = s1; red2[wid] = s2; }
    __syncthreads();
    if (wid == 0) {
        s1 = (lane < NTHREADS / 32) ? red1[lane] : 0.f;
        s2 = (lane < NTHREADS / 32) ? red2[lane] : 0.f;
        #pragma unroll
        for (int off = 4; off > 0; off >>= 1) {
            s1 += __shfl_down_sync(0xFFFFFFFFu, s1, off);
            s2 += __shfl_down_sync(0xFFFFFFFFu, s2, off);
        }
        if (lane == 0) {
            atomicAdd(&g_sum[c], s1);
            atomicAdd(&g_sumsq[c], s2);
        }
    }
}

// Fold mean/var/gamma/beta into per-channel scale & shift.
__global__ void finalize_kernel(const float* __restrict__ gamma,
                                const float* __restrict__ beta) {
    int c = threadIdx.x;
    if (c < CCH) {
        float mean = g_sum[c] / NHW_F;
        float var  = g_sumsq[c] / NHW_F - mean * mean;
        float sc   = gamma[c] * rsqrtf(var + BN_EPS);
        g_scale[c] = sc;
        g_shift[c] = beta[c] - sc * mean;
    }
}

// Pass 2: recompute conv+bias, apply scale/shift + ReLU6, write float4.
__global__ void __launch_bounds__(NTHREADS)
output_kernel(const float* __restrict__ in,
              const float* __restrict__ w,
              const float* __restrict__ b,
              float* __restrict__ out) {
    __shared__ __align__(16) float sm[SMEMN];

    int h0 = blockIdx.x * TILE_H;
    int c  = blockIdx.y;
    int n  = blockIdx.z;

    const float* base = in + (size_t)(n * CCH + c) * IMG;
    load_tile(base, h0, sm);

    float k[9];
    #pragma unroll
    for (int i = 0; i < 9; i++) k[i] = __ldg(w + c * 9 + i);
    float bias = __ldg(b + c);
    float sc = g_scale[c];
    float sh = g_shift[c];
    __syncthreads();

    int ry = threadIdx.x / 28;
    int x4 = (threadIdx.x - ry * 28) * 4;

    float a[4], bb[4];
    conv42(sm, k, bias, ry, x4, a, bb);

    float4 oa, ob;
    oa.x = fminf(fmaxf(a[0]  * sc + sh, 0.f), 6.f);
    oa.y = fminf(fmaxf(a[1]  * sc + sh, 0.f), 6.f);
    oa.z = fminf(fmaxf(a[2]  * sc + sh, 0.f), 6.f);
    oa.w = fminf(fmaxf(a[3]  * sc + sh, 0.f), 6.f);
    ob.x = fminf(fmaxf(bb[0] * sc + sh, 0.f), 6.f);
    ob.y = fminf(fmaxf(bb[1] * sc + sh, 0.f), 6.f);
    ob.z = fminf(fmaxf(bb[2] * sc + sh, 0.f), 6.f);
    ob.w = fminf(fmaxf(bb[3] * sc + sh, 0.f), 6.f);

    float* obase = out + (size_t)(n * CCH + c) * IMG + (h0 + 2 * ry) * HW + x4;
    *reinterpret_cast<float4*>(obase)      = oa;
    *reinterpret_cast<float4*>(obase + HW) = ob;
}

extern "C" void kernel_launch(void* const* d_in, const int* in_sizes, int n_in,
                              void* d_out, int out_size) {
    const float* in    = (const float*)d_in[0];
    const float* w     = (const float*)d_in[1];
    const float* b     = (const float*)d_in[2];
    const float* gamma = (const float*)d_in[3];
    const float* beta  = (const float*)d_in[4];
    float* out = (float*)d_out;

    dim3 grid(TILES, CCH, NB);  // 7 x 192 x 32 = 43008 blocks
    zero_stats_kernel<<<1, CCH>>>();
    stats_kernel<<<grid, NTHREADS>>>(in, w, b);
    finalize_kernel<<<1, CCH>>>(gamma, beta);
    output_kernel<<<grid, NTHREADS>>>(in, w, b, out);
}

// round 3
// speedup vs baseline: 2.3070x; 1.6398x over previous
#include <cuda_runtime.h>

#define NB      32
#define CCH     192
#define HW      112
#define IMG     (HW*HW)           // 12544
#define TILE_H  16                // rows per block (4 warps x 4 rows)
#define TILES   (HW / TILE_H)     // 7
#define NHW_F   ((float)(NB * IMG))
#define BN_EPS  1e-5f

// Scratch for channel statistics / folded affine params (no cudaMalloc allowed)
__device__ float g_sum[CCH];      // sum of raw conv (no bias)
__device__ float g_sumsq[CCH];    // sum of raw conv^2
__device__ float g_scale[CCH];
__device__ float g_shift[CCH];

__global__ void zero_stats_kernel() {
    int i = threadIdx.x;
    if (i < CCH) { g_sum[i] = 0.f; g_sumsq[i] = 0.f; }
}

// Load 6 input rows (h-1 .. h+4) as float4 per lane; lanes >=28 and OOB rows get 0.
__device__ __forceinline__ void load_rows(const float* __restrict__ base,
                                          int h, int lane, bool active,
                                          float4* v) {
    #pragma unroll
    for (int r = 0; r < 6; r++) {
        int row = h - 1 + r;
        float4 t = make_float4(0.f, 0.f, 0.f, 0.f);
        if (active && (unsigned)row < HW)
            t = __ldg(reinterpret_cast<const float4*>(base + row * HW) + lane);
        v[r] = t;
    }
}

// Accumulate conv for a 4x4 micro-tile (acc[j][i], j=row 0..3, i=col 0..3), no bias.
__device__ __forceinline__ void conv44(const float4* v, const float* __restrict__ k,
                                       int lane, float acc[4][4]) {
    #pragma unroll
    for (int j = 0; j < 4; j++)
        #pragma unroll
        for (int i = 0; i < 4; i++)
            acc[j][i] = 0.f;

    #pragma unroll
    for (int r = 0; r < 6; r++) {
        float left  = __shfl_up_sync(0xFFFFFFFFu, v[r].w, 1);
        float right = __shfl_down_sync(0xFFFFFFFFu, v[r].x, 1);
        if (lane == 0) left = 0.f;
        float p[6] = { left, v[r].x, v[r].y, v[r].z, v[r].w, right };
        // input row (h-1+r) feeds output row j with kernel-row (r - j), j in [r-2, r]
        #pragma unroll
        for (int j = 0; j < 4; j++) {
            if (j >= r - 2 && j <= r) {
                const float k0 = k[3 * (r - j) + 0];
                const float k1 = k[3 * (r - j) + 1];
                const float k2 = k[3 * (r - j) + 2];
                #pragma unroll
                for (int i = 0; i < 4; i++)
                    acc[j][i] += k0 * p[i] + k1 * p[i + 1] + k2 * p[i + 2];
            }
        }
    }
}

// Pass 1: per-channel sums of conv and conv^2 (bias folded in analytically later).
__global__ void __launch_bounds__(128)
stats_kernel(const float* __restrict__ in,
             const float* __restrict__ w) {
    __shared__ float red1[4];
    __shared__ float red2[4];

    int lane = threadIdx.x & 31;
    int wid  = threadIdx.x >> 5;
    int c = blockIdx.y, n = blockIdx.z;
    int h = blockIdx.x * TILE_H + wid * 4;
    bool active = lane < 28;

    const float* base = in + (size_t)(n * CCH + c) * IMG;
    float k[9];
    #pragma unroll
    for (int i = 0; i < 9; i++) k[i] = __ldg(w + c * 9 + i);

    float4 v[6];
    load_rows(base, h, lane, active, v);

    float acc[4][4];
    conv44(v, k, lane, acc);

    float s1 = 0.f, s2 = 0.f;
    if (active) {
        #pragma unroll
        for (int j = 0; j < 4; j++)
            #pragma unroll
            for (int i = 0; i < 4; i++) {
                s1 += acc[j][i];
                s2 += acc[j][i] * acc[j][i];
            }
    }

    #pragma unroll
    for (int off = 16; off > 0; off >>= 1) {
        s1 += __shfl_down_sync(0xFFFFFFFFu, s1, off);
        s2 += __shfl_down_sync(0xFFFFFFFFu, s2, off);
    }
    if (lane == 0) { red1[wid] = s1; red2[wid] = s2; }
    __syncthreads();
    if (threadIdx.x == 0) {
        atomicAdd(&g_sum[c],   red1[0] + red1[1] + red1[2] + red1[3]);
        atomicAdd(&g_sumsq[c], red2[0] + red2[1] + red2[2] + red2[3]);
    }
}

// Fold bias/mean/var/gamma/beta into per-channel scale & shift.
__global__ void finalize_kernel(const float* __restrict__ b,
                                const float* __restrict__ gamma,
                                const float* __restrict__ beta) {
    int c = threadIdx.x;
    if (c < CCH) {
        float bias   = b[c];
        float sum_y  = g_sum[c] + NHW_F * bias;
        float ssq_y  = g_sumsq[c] + 2.f * bias * g_sum[c] + NHW_F * bias * bias;
        float mean   = sum_y / NHW_F;
        float var    = ssq_y / NHW_F - mean * mean;
        float sc     = gamma[c] * rsqrtf(var + BN_EPS);
        g_scale[c] = sc;
        g_shift[c] = beta[c] + sc * (bias - mean);
    }
}

// Pass 2: recompute conv, apply folded scale/shift + ReLU6, write float4.
__global__ void __launch_bounds__(128)
output_kernel(const float* __restrict__ in,
              const float* __restrict__ w,
              float* __restrict__ out) {
    int lane = threadIdx.x & 31;
    int wid  = threadIdx.x >> 5;
    int c = blockIdx.y, n = blockIdx.z;
    int h = blockIdx.x * TILE_H + wid * 4;
    bool active = lane < 28;

    const float* base = in + (size_t)(n * CCH + c) * IMG;
    float k[9];
    #pragma unroll
    for (int i = 0; i < 9; i++) k[i] = __ldg(w + c * 9 + i);
    float sc = g_scale[c];
    float sh = g_shift[c];

    float4 v[6];
    load_rows(base, h, lane, active, v);

    float acc[4][4];
    conv44(v, k, lane, acc);

    if (active) {
        float* ob = out + (size_t)(n * CCH + c) * IMG + h * HW + lane * 4;
        #pragma unroll
        for (int j = 0; j < 4; j++) {
            float4 o;
            o.x = fminf(fmaxf(fmaf(acc[j][0], sc, sh), 0.f), 6.f);
            o.y = fminf(fmaxf(fmaf(acc[j][1], sc, sh), 0.f), 6.f);
            o.z = fminf(fmaxf(fmaf(acc[j][2], sc, sh), 0.f), 6.f);
            o.w = fminf(fmaxf(fmaf(acc[j][3], sc, sh), 0.f), 6.f);
            *reinterpret_cast<float4*>(ob + j * HW) = o;
        }
    }
}

extern "C" void kernel_launch(void* const* d_in, const int* in_sizes, int n_in,
                              void* d_out, int out_size) {
    const float* in    = (const float*)d_in[0];
    const float* w     = (const float*)d_in[1];
    const float* b     = (const float*)d_in[2];
    const float* gamma = (const float*)d_in[3];
    const float* beta  = (const float*)d_in[4];
    float* out = (float*)d_out;

    dim3 grid(TILES, CCH, NB);  // 7 x 192 x 32 = 43008 blocks, 128 threads each
    zero_stats_kernel<<<1, CCH>>>();
    stats_kernel<<<grid, 128>>>(in, w);
    finalize_kernel<<<1, CCH>>>(b, gamma, beta);
    output_kernel<<<grid, 128>>>(in, w, out);
}